// round 4
// baseline (speedup 1.0000x reference)
#include <cuda_runtime.h>
#include <math.h>

#define HH 384
#define WW 384
#define NPIX (HH*WW)          // 147456
#define BB 2
#define BN (BB*NPIX)          // 294912
#define NDIR 128

// ======================= scratch buffers =======================
__device__ float g_P[BN];
__device__ float g_E[BN];
__device__ float g_S[BN];
__device__ float g_Lp[BN];
__device__ float g_zb[BN];
__device__ float g_R[2*BN];      // [(b*2+k)*NPIX+n]
__device__ float g_Ra[2*BN];
__device__ float g_DM[BN];
__device__ float g_t0[2*BN], g_t1[2*BN], g_t2[2*BN];
__device__ float g_lla[2*BN];
__device__ float g_den[2*BN];
__device__ float g_gld[2*BN];
__device__ float g_La[BN];
__device__ unsigned char g_idxb[BN];
__device__ float g_colsum[(size_t)4*NPIX*32];   // [bk][y][x][bin]

// ======================= small state =======================
__device__ float    g_sv[64];
__device__ unsigned g_selpref[64];
__device__ int      g_selrank[64];
__device__ unsigned g_selhist[64*256];
__device__ unsigned g_mm[BB][2] = {{0xFFFFFFFFu,0u},{0xFFFFFFFFu,0u}};
__device__ double   g_reg[BB][5];
__device__ double   g_beta[BB][2];
__device__ double   g_cacc[BB][9];
__device__ double   g_mean3[BB][3];
__device__ double   g_wwh[BB][9];
__device__ float    g_cdir[BB*NDIR*3];
__device__ float    g_cbest[BB][3];
__device__ double   g_dirm[BB][NDIR][4];
__device__ double   g_emacc[BB][6];
__device__ double   g_empar[BB][6];   // mu0 mu1 var0 var1 pi0 pi1
__device__ double   g_clacc[BB][2][10];
__device__ double   g_clmu[BB][2][3];
__device__ double   g_clinv[BB][2][9];
__device__ double   g_ghist[BB][2][32];
__device__ float    g_gcdf[BB][2][32];
__device__ double   g_esinv[BB][6];   // i00 i01 i11 meanE meanS

// ======================= helpers =======================
static __device__ __forceinline__ unsigned f2u(float f){
    unsigned u = __float_as_uint(f);
    return (u & 0x80000000u) ? ~u : (u | 0x80000000u);
}
static __device__ __forceinline__ float u2f(unsigned u){
    unsigned v = (u & 0x80000000u) ? (u & 0x7FFFFFFFu) : ~u;
    return __uint_as_float(v);
}
static __device__ __forceinline__ float softplusf(float x){
    float t = log1pf(expf(-fabsf(x)));
    return x >= 0.f ? x + t : t;
}
static __device__ double blockReduceD(double v){
    __shared__ double sh[32];
    int lane = threadIdx.x & 31, wid = threadIdx.x >> 5;
    for (int o=16;o;o>>=1) v += __shfl_down_sync(0xffffffffu, v, o);
    if (lane==0) sh[wid] = v;
    __syncthreads();
    int nw = (blockDim.x + 31) >> 5;
    v = (threadIdx.x < nw) ? sh[threadIdx.x] : 0.0;
    if (wid==0) for (int o=16;o;o>>=1) v += __shfl_down_sync(0xffffffffu, v, o);
    __syncthreads();
    return v;
}
static __device__ void eigh3(const double* A, double* e, double* V){
    double a[9]; for(int i=0;i<9;i++) a[i]=A[i];
    for(int i=0;i<9;i++) V[i] = (i%4==0)?1.0:0.0;
    for(int sweep=0;sweep<40;sweep++){
        double off = fabs(a[1])+fabs(a[2])+fabs(a[5]);
        if(off < 1e-300) break;
        for(int p=0;p<2;p++) for(int q=p+1;q<3;q++){
            double apq=a[p*3+q];
            if(fabs(apq) < 1e-300) continue;
            double app=a[p*3+p], aqq=a[q*3+q];
            double th=(aqq-app)/(2.0*apq);
            double t=(th>=0?1.0:-1.0)/(fabs(th)+sqrt(th*th+1.0));
            double c=1.0/sqrt(t*t+1.0), s=t*c;
            for(int i=0;i<3;i++){ double x=a[i*3+p],y=a[i*3+q]; a[i*3+p]=c*x-s*y; a[i*3+q]=s*x+c*y; }
            for(int i=0;i<3;i++){ double x=a[p*3+i],y=a[q*3+i]; a[p*3+i]=c*x-s*y; a[q*3+i]=s*x+c*y; }
            for(int i=0;i<3;i++){ double x=V[i*3+p],y=V[i*3+q]; V[i*3+p]=c*x-s*y; V[i*3+q]=s*x+c*y; }
        }
    }
    e[0]=a[0]; e[1]=a[4]; e[2]=a[8];
}
static __device__ void inv3(const double* m, double* inv){
    double a=m[0],b=m[1],c=m[2],d=m[3],e=m[4],f=m[5],g=m[6],h=m[7],i=m[8];
    double A=e*i-f*h, B=c*h-b*i, C=b*f-c*e;
    double D=f*g-d*i, E=a*i-c*g, F=c*d-a*f;
    double G=d*h-e*g, Hh=b*g-a*h, I=a*e-b*d;
    double det=a*A+b*D+c*G, id=1.0/det;
    inv[0]=A*id; inv[1]=B*id; inv[2]=C*id;
    inv[3]=D*id; inv[4]=E*id; inv[5]=F*id;
    inv[6]=G*id; inv[7]=Hh*id; inv[8]=I*id;
}

// ======================= select jobs =======================
// {type, b, rank, mode, refSlot, outSlot}
__device__ const int g_jobs[44*6] = {
 0,0,73727,0,0,0,  1,0,73727,0,0,1,  2,0,73727,0,0,2,
 0,1,73727,0,0,3,  1,1,73727,0,0,4,  2,1,73727,0,0,5,
 0,0,73727,1,0,6,  1,0,73727,1,1,7,  2,0,73727,1,2,8,
 0,1,73727,1,3,9,  1,1,73727,1,4,10, 2,1,73727,1,5,11,
 3,0,36863,0,0,12, 3,0,36864,0,0,13, 3,0,110591,0,0,14, 3,0,110592,0,0,15,
 3,1,36863,0,0,16, 3,1,36864,0,0,17, 3,1,110591,0,0,18, 3,1,110592,0,0,19,
 4,0,73727,0,0,20, 5,0,73727,0,0,21, 4,1,73727,0,0,22, 5,1,73727,0,0,23,
 4,0,73727,1,20,24, 5,0,73727,1,21,25, 4,1,73727,1,22,26, 5,1,73727,1,23,27,
 6,0,73727,0,0,28, 7,0,73727,0,0,29, 6,1,73727,0,0,30, 7,1,73727,0,0,31,
 6,0,73727,1,28,32, 7,0,73727,1,29,33, 6,1,73727,1,30,34, 7,1,73727,1,31,35,
 8,0,1474,0,0,36, 8,0,1475,0,0,37, 8,0,145980,0,0,38, 8,0,145981,0,0,39,
 8,1,1474,0,0,40, 8,1,1475,0,0,41, 8,1,145980,0,0,42, 8,1,145981,0,0,43
};

static __device__ const float* selSrc(int type, int b){
    switch(type){
        case 0: return g_Lp + b*NPIX;
        case 1: return g_E  + b*NPIX;
        case 2: return g_S  + b*NPIX;
        case 3: return g_zb + b*NPIX;
        case 4: return g_lla + (b*2+0)*NPIX;
        case 5: return g_lla + (b*2+1)*NPIX;
        case 6: return g_gld + (b*2+0)*NPIX;
        case 7: return g_gld + (b*2+1)*NPIX;
        default: return g_La + b*NPIX;
    }
}

__global__ void selCount(int phaseStart, int pass){
    int j = phaseStart + blockIdx.x;
    const int* jb = &g_jobs[j*6];
    const float* src = selSrc(jb[0], jb[1]);
    int mode = jb[3];
    float ref = mode ? g_sv[jb[4]] : 0.f;
    unsigned pref = (pass==0)?0u:g_selpref[j];
    int shift = 24 - 8*pass;
    __shared__ unsigned sh[256];
    for(int i=threadIdx.x;i<256;i+=blockDim.x) sh[i]=0;
    __syncthreads();
    int per = (NPIX + gridDim.y - 1)/gridDim.y;
    int lo = blockIdx.y*per, hi = min(lo+per, NPIX);
    for(int i=lo+threadIdx.x;i<hi;i+=blockDim.x){
        float v = src[i]; if(mode) v = fabsf(v - ref);
        unsigned key = f2u(v);
        if(pass==0 || ((key ^ pref) >> (shift+8)) == 0)
            atomicAdd(&sh[(key>>shift)&255],1u);
    }
    __syncthreads();
    for(int i=threadIdx.x;i<256;i+=blockDim.x)
        if(sh[i]) atomicAdd(&g_selhist[j*256+i], sh[i]);
}

__global__ void selPick(int phaseStart, int pass){
    int j = phaseStart + blockIdx.x;
    const int* jb = &g_jobs[j*6];
    if(threadIdx.x==0){
        long long rank = (pass==0)?(long long)jb[2]:(long long)g_selrank[j];
        unsigned pref = (pass==0)?0u:g_selpref[j];
        int shift = 24 - 8*pass;
        long long cum=0; int bucket=255;
        for(int i=0;i<256;i++){
            unsigned c = g_selhist[j*256+i];
            if(cum + (long long)c > rank){ bucket=i; break; }
            cum += c;
        }
        rank -= cum;
        pref |= ((unsigned)bucket) << shift;
        if(pass==3) g_sv[jb[5]] = u2f(pref);
        g_selrank[j]=(int)rank; g_selpref[j]=pref;
    }
    __syncthreads();
    for(int i=threadIdx.x;i<256;i+=blockDim.x) g_selhist[j*256+i]=0;
}

// ======================= pipeline kernels =======================
__global__ void kSobel(const float* lab){
    int idx = blockIdx.x*blockDim.x + threadIdx.x;
    if(idx >= BN) return;
    int b = idx / NPIX, p = idx % NPIX;
    int y = p / WW, x = p % WW;
    const float* L = lab + (size_t)b*3*NPIX;
    #define AT(yy,xx) (((yy)>=0&&(yy)<HH&&(xx)>=0&&(xx)<WW)?L[(yy)*WW+(xx)]:0.f)
    float l00=AT(y-1,x-1), l01=AT(y-1,x), l02=AT(y-1,x+1);
    float l10=AT(y,x-1),                  l12=AT(y,x+1);
    float l20=AT(y+1,x-1), l21=AT(y+1,x), l22=AT(y+1,x+1);
    #undef AT
    float gx = -l00 + l02 - 2.f*l10 + 2.f*l12 - l20 + l22;
    float gy = -l00 - 2.f*l01 - l02 + l20 + 2.f*l21 + l22;
    g_P[idx] = gx*gx + gy*gy;
    float av = L[NPIX + p], bv = L[2*NPIX + p];
    g_S[idx] = sqrtf(av*av + bv*bv + 1e-8f);
}

__global__ void kE(){
    int idx = blockIdx.x*blockDim.x + threadIdx.x;
    if(idx >= BN) return;
    int b = idx / NPIX, p = idx % NPIX;
    int y = p / WW, x = p % WW;
    float s = 0.f;
    for(int dy=-1;dy<=1;dy++){ int yy=y+dy; if(yy<0||yy>=HH) continue;
      for(int dx=-1;dx<=1;dx++){ int xx=x+dx; if(xx<0||xx>=WW) continue;
        s += g_P[b*NPIX + yy*WW + xx]; } }
    g_E[idx] = s / 9.f;
}

__global__ void kRegAcc(const float* lab){
    int b = blockIdx.y;
    double a0=0,a1=0,a2=0,a3=0,a4=0;
    int per = (NPIX + gridDim.x - 1)/gridDim.x;
    int lo = blockIdx.x*per, hi = min(lo+per, NPIX);
    for(int p=lo+threadIdx.x;p<hi;p+=blockDim.x){
        double e=g_E[b*NPIX+p], s=g_S[b*NPIX+p], l=lab[(size_t)b*3*NPIX+p];
        a0+=e*e; a1+=e*s; a2+=s*s; a3+=e*l; a4+=s*l;
    }
    double r;
    r=blockReduceD(a0); if(threadIdx.x==0) atomicAdd(&g_reg[b][0],r);
    r=blockReduceD(a1); if(threadIdx.x==0) atomicAdd(&g_reg[b][1],r);
    r=blockReduceD(a2); if(threadIdx.x==0) atomicAdd(&g_reg[b][2],r);
    r=blockReduceD(a3); if(threadIdx.x==0) atomicAdd(&g_reg[b][3],r);
    r=blockReduceD(a4); if(threadIdx.x==0) atomicAdd(&g_reg[b][4],r);
}

__global__ void kSolve(){
    int b = threadIdx.x; if(b>=BB) return;
    double ee=g_reg[b][0]+1e-6, es=g_reg[b][1], ss=g_reg[b][2]+1e-6;
    double el=g_reg[b][3], sl=g_reg[b][4];
    double det = ee*ss - es*es;
    g_beta[b][0] = (ss*el - es*sl)/det;
    g_beta[b][1] = (ee*sl - es*el)/det;
    for(int i=0;i<5;i++) g_reg[b][i]=0.0;
}

__global__ void kLperp(const float* lab, float* out){
    int idx = blockIdx.x*blockDim.x + threadIdx.x;
    if(idx >= BN) return;
    int b = idx / NPIX, p = idx % NPIX;
    float v = lab[(size_t)b*3*NPIX+p] - (float)g_beta[b][0]*g_E[idx] - (float)g_beta[b][1]*g_S[idx];
    g_Lp[idx] = v;
    out[idx] = v;   // output #1
}

__global__ void kCovAcc(){
    int b = blockIdx.y;
    float md[3], sd[3];
    for(int f=0;f<3;f++){ md[f]=g_sv[b*3+f]; sd[f]=g_sv[6+b*3+f]*1.4826f+1e-8f; }
    double a[9]={0,0,0,0,0,0,0,0,0};
    int per = (NPIX + gridDim.x - 1)/gridDim.x;
    int lo = blockIdx.x*per, hi = min(lo+per, NPIX);
    for(int p=lo+threadIdx.x;p<hi;p+=blockDim.x){
        float z0=(g_Lp[b*NPIX+p]-md[0])/sd[0];
        float z1=(g_E [b*NPIX+p]-md[1])/sd[1];
        float z2=(g_S [b*NPIX+p]-md[2])/sd[2];
        a[0]+=z0; a[1]+=z1; a[2]+=z2;
        a[3]+=(double)z0*z0; a[4]+=(double)z0*z1; a[5]+=(double)z0*z2;
        a[6]+=(double)z1*z1; a[7]+=(double)z1*z2; a[8]+=(double)z2*z2;
    }
    for(int m=0;m<9;m++){ double r=blockReduceD(a[m]); if(threadIdx.x==0) atomicAdd(&g_cacc[b][m],r); }
}

__global__ void kEigh(){
    int b = threadIdx.x; if(b>=BB) return;
    double N = (double)NPIX;
    double mu[3]; for(int i=0;i<3;i++){ mu[i]=g_cacc[b][i]/N; g_mean3[b][i]=mu[i]; }
    double C[9];
    C[0]=g_cacc[b][3]/N-mu[0]*mu[0]; C[1]=g_cacc[b][4]/N-mu[0]*mu[1]; C[2]=g_cacc[b][5]/N-mu[0]*mu[2];
    C[4]=g_cacc[b][6]/N-mu[1]*mu[1]; C[5]=g_cacc[b][7]/N-mu[1]*mu[2]; C[8]=g_cacc[b][8]/N-mu[2]*mu[2];
    C[3]=C[1]; C[6]=C[2]; C[7]=C[5];
    for(int i=0;i<9;i++) C[i] = C[i] > 1e-8 ? C[i] : 1e-8;   // elementwise max, matches reference
    double e[3], V[9];
    eigh3(C, e, V);
    for(int i=0;i<3;i++) for(int j=0;j<3;j++){
        double s=0; for(int k2=0;k2<3;k2++) s += V[i*3+k2]*(1.0/sqrt(e[k2]))*V[j*3+k2];
        g_wwh[b][i*3+j]=s;
    }
    for(int i=0;i<9;i++) g_cacc[b][i]=0.0;
}

__global__ void kCdir(const float* arand){
    int t = threadIdx.x; if(t>=BB*NDIR) return;
    int b = t / NDIR, d = t % NDIR;
    float a0=arand[(b*NDIR+d)*3+0], a1=arand[(b*NDIR+d)*3+1], a2=arand[(b*NDIR+d)*3+2];
    float nr = sqrtf(a0*a0+a1*a1+a2*a2) + 1e-12f;
    double an[3]={a0/nr,a1/nr,a2/nr};
    for(int j=0;j<3;j++){
        double s=0; for(int i=0;i<3;i++) s += g_wwh[b][j*3+i]*an[i];
        g_cdir[(b*NDIR+d)*3+j]=(float)s;
    }
}

__global__ void kKurtAcc(){
    int b = blockIdx.z, g8 = blockIdx.y*8;
    float md[3], sd[3], mn[3];
    for(int f=0;f<3;f++){ md[f]=g_sv[b*3+f]; sd[f]=g_sv[6+b*3+f]*1.4826f+1e-8f; mn[f]=(float)g_mean3[b][f]; }
    float c[8][3];
    for(int d=0;d<8;d++) for(int j=0;j<3;j++) c[d][j]=g_cdir[(b*NDIR+g8+d)*3+j];
    float acc[32];
    for(int i=0;i<32;i++) acc[i]=0.f;
    int per = (NPIX + gridDim.x - 1)/gridDim.x;
    int lo = blockIdx.x*per, hi = min(lo+per, NPIX);
    for(int p=lo+threadIdx.x;p<hi;p+=blockDim.x){
        float d0=(g_Lp[b*NPIX+p]-md[0])/sd[0]-mn[0];
        float d1=(g_E [b*NPIX+p]-md[1])/sd[1]-mn[1];
        float d2=(g_S [b*NPIX+p]-md[2])/sd[2]-mn[2];
        #pragma unroll
        for(int d=0;d<8;d++){
            float z = d0*c[d][0]+d1*c[d][1]+d2*c[d][2];
            float z2=z*z;
            acc[d*4+0]+=z; acc[d*4+1]+=z2; acc[d*4+2]+=z2*z; acc[d*4+3]+=z2*z2;
        }
    }
    __shared__ float sh[256];
    for(int v=0; v<32; v++){
        sh[threadIdx.x]=acc[v];
        __syncthreads();
        for(int o=128;o>0;o>>=1){ if(threadIdx.x<o) sh[threadIdx.x]+=sh[threadIdx.x+o]; __syncthreads(); }
        if(threadIdx.x==0) atomicAdd(&g_dirm[b][g8+v/4][v%4],(double)sh[0]);
        __syncthreads();
    }
}

__global__ void kKurtPick(){
    int b = threadIdx.x; if(b>=BB) return;
    double N=(double)NPIX, bestv=-1.0; int best=0;
    for(int d=0;d<NDIR;d++){
        double m1=g_dirm[b][d][0]/N, s2=g_dirm[b][d][1]/N, s3=g_dirm[b][d][2]/N, s4=g_dirm[b][d][3]/N;
        double m2=(s2-m1*m1)+1e-12;
        double m4=s4-4.0*m1*s3+6.0*m1*m1*s2-3.0*m1*m1*m1*m1;
        double kurt=fabs(m4/(m2*m2)-3.0);
        if(kurt>bestv){bestv=kurt;best=d;}
    }
    for(int j=0;j<3;j++) g_cbest[b][j]=g_cdir[(b*NDIR+best)*3+j];
    for(int d=0;d<NDIR;d++) for(int m=0;m<4;m++) g_dirm[b][d][m]=0.0;
}

__global__ void kZb(){
    int idx = blockIdx.x*blockDim.x + threadIdx.x;
    if(idx >= BN) return;
    int b = idx / NPIX, p = idx % NPIX;
    float md0=g_sv[b*3+0], md1=g_sv[b*3+1], md2=g_sv[b*3+2];
    float sd0=g_sv[6+b*3+0]*1.4826f+1e-8f, sd1=g_sv[6+b*3+1]*1.4826f+1e-8f, sd2=g_sv[6+b*3+2]*1.4826f+1e-8f;
    float d0=(g_Lp[idx]-md0)/sd0-(float)g_mean3[b][0];
    float d1=(g_E [idx]-md1)/sd1-(float)g_mean3[b][1];
    float d2=(g_S [idx]-md2)/sd2-(float)g_mean3[b][2];
    g_zb[idx] = d0*g_cbest[b][0]+d1*g_cbest[b][1]+d2*g_cbest[b][2];
}

__global__ void kEMinit(){
    int b = threadIdx.x; if(b>=BB) return;
    float q25 = g_sv[12+4*b] + 0.75f*(g_sv[13+4*b]-g_sv[12+4*b]);
    float q75 = g_sv[14+4*b] + 0.25f*(g_sv[15+4*b]-g_sv[14+4*b]);
    g_empar[b][0]=q25; g_empar[b][1]=q75;
    g_empar[b][2]=1.0; g_empar[b][3]=1.0;
    g_empar[b][4]=0.5; g_empar[b][5]=0.5;
}

static __device__ __forceinline__ void emResp(int b, float x, float& R0, float& R1){
    float mu0=(float)g_empar[b][0], mu1=(float)g_empar[b][1];
    float v0=(float)g_empar[b][2]+1e-6f, v1=(float)g_empar[b][3]+1e-6f;
    float lp0=-0.5f*(x-mu0)*(x-mu0)/v0 - 0.5f*logf(v0) + logf((float)g_empar[b][4]+1e-8f);
    float lp1=-0.5f*(x-mu1)*(x-mu1)/v1 - 0.5f*logf(v1) + logf((float)g_empar[b][5]+1e-8f);
    R0 = 1.f/(1.f+expf(lp1-lp0));
    R1 = 1.f/(1.f+expf(lp0-lp1));
}

__global__ void kEMacc(){
    int b = blockIdx.y;
    float a[6]={0,0,0,0,0,0};
    int per = (NPIX + gridDim.x - 1)/gridDim.x;
    int lo = blockIdx.x*per, hi = min(lo+per, NPIX);
    for(int p=lo+threadIdx.x;p<hi;p+=blockDim.x){
        float x = g_zb[b*NPIX+p], R0, R1;
        emResp(b, x, R0, R1);
        a[0]+=R0; a[1]+=R0*x; a[2]+=R0*x*x;
        a[3]+=R1; a[4]+=R1*x; a[5]+=R1*x*x;
    }
    for(int m=0;m<6;m++){ double r=blockReduceD((double)a[m]); if(threadIdx.x==0) atomicAdd(&g_emacc[b][m],r); }
}

__global__ void kEMupd(){
    int b = threadIdx.x; if(b>=BB) return;
    for(int k=0;k<2;k++){
        double Sr=g_emacc[b][k*3], Sx=g_emacc[b][k*3+1], Sxx=g_emacc[b][k*3+2];
        double den = Sr + 1e-8;
        double mu = Sx/den;
        double var = (Sxx - 2.0*mu*Sx + mu*mu*Sr)/den + 1e-6;
        g_empar[b][k]=mu; g_empar[b][2+k]=var; g_empar[b][4+k]=Sr/(double)NPIX;
    }
    for(int m=0;m<6;m++) g_emacc[b][m]=0.0;
}

__global__ void kRfinal(){
    int idx = blockIdx.x*blockDim.x + threadIdx.x;
    if(idx >= BN) return;
    int b = idx / NPIX, p = idx % NPIX;
    float R0, R1;
    emResp(b, g_zb[idx], R0, R1);
    g_R[(b*2+0)*NPIX+p]=R0;
    g_R[(b*2+1)*NPIX+p]=R1;
}

__global__ void kRalpha(){
    int idx = blockIdx.x*blockDim.x + threadIdx.x;
    if(idx >= BN) return;
    int b = idx / NPIX, p = idx % NPIX;
    float r0=powf(g_R[(b*2+0)*NPIX+p],0.9f);
    float r1=powf(g_R[(b*2+1)*NPIX+p],0.9f);
    float s = r0+r1+1e-8f;
    g_Ra[(b*2+0)*NPIX+p]=r0/s;
    g_Ra[(b*2+1)*NPIX+p]=r1/s;
}

__global__ void kClusterAcc(){
    int bk = blockIdx.y; int b=bk>>1, k=bk&1;
    double a[10]={0,0,0,0,0,0,0,0,0,0};
    int per = (NPIX + gridDim.x - 1)/gridDim.x;
    int lo = blockIdx.x*per, hi = min(lo+per, NPIX);
    for(int p=lo+threadIdx.x;p<hi;p+=blockDim.x){
        double w=g_Ra[bk*NPIX+p];
        double x0=g_Lp[b*NPIX+p], x1=g_E[b*NPIX+p], x2=g_S[b*NPIX+p];
        a[0]+=w; a[1]+=w*x0; a[2]+=w*x1; a[3]+=w*x2;
        a[4]+=w*x0*x0; a[5]+=w*x0*x1; a[6]+=w*x0*x2;
        a[7]+=w*x1*x1; a[8]+=w*x1*x2; a[9]+=w*x2*x2;
    }
    for(int m=0;m<10;m++){ double r=blockReduceD(a[m]); if(threadIdx.x==0) atomicAdd(&g_clacc[b][k][m],r); }
}

__global__ void kClusterInv(){
    int t = threadIdx.x; if(t>=4) return;
    int b=t>>1, k=t&1;
    double* A = g_clacc[b][k];
    double Ws = A[0] + 1e-8;
    double mu[3] = {A[1]/Ws, A[2]/Ws, A[3]/Ws};
    double Sx[3] = {A[1], A[2], A[3]};
    double Sxx[9] = {A[4],A[5],A[6], A[5],A[7],A[8], A[6],A[8],A[9]};
    double C[9];
    for(int i=0;i<3;i++) for(int j=0;j<3;j++)
        C[i*3+j] = (Sxx[i*3+j] - mu[i]*Sx[j] - mu[j]*Sx[i] + A[0]*mu[i]*mu[j])/Ws + ((i==j)?1e-6:0.0);
    double I[9]; inv3(C, I);
    for(int i=0;i<9;i++) g_clinv[b][k][i]=I[i];
    for(int i=0;i<3;i++) g_clmu[b][k][i]=mu[i];
    for(int i=0;i<10;i++) A[i]=0.0;
}

__global__ void kDM(){
    int idx = blockIdx.x*blockDim.x + threadIdx.x;
    if(idx >= BN) return;
    int b = idx / NPIX, p = idx % NPIX;
    float X[3] = {g_Lp[idx], g_E[idx], g_S[idx]};
    float ra0=g_Ra[(b*2+0)*NPIX+p], ra1=g_Ra[(b*2+1)*NPIX+p];
    float ssum = ra0+ra1+2e-8f;
    float DM=0.f;
    for(int k=0;k<2;k++){
        float xm0=X[0]-(float)g_clmu[b][k][0];
        float xm1=X[1]-(float)g_clmu[b][k][1];
        float xm2=X[2]-(float)g_clmu[b][k][2];
        const double* I=g_clinv[b][k];
        float q = xm0*xm0*(float)I[0] + xm1*xm1*(float)I[4] + xm2*xm2*(float)I[8]
                + 2.f*xm0*xm1*(float)I[1] + 2.f*xm0*xm2*(float)I[2] + 2.f*xm1*xm2*(float)I[5];
        float Dk = sqrtf(q + 1e-8f);
        float Rt = ((k==0?ra0:ra1)+1e-8f)/ssum;
        DM += Rt*Dk;
    }
    g_DM[idx]=DM;
}

__global__ void kBoxH(){
    int bk = blockIdx.y; int b=bk>>1;
    int p = blockIdx.x*blockDim.x + threadIdx.x;
    if(p >= NPIX) return;
    int y = p / WW, x = p % WW;
    float s0=0.f,s1=0.f,s2=0.f;
    int lo = max(x-7,0), hi = min(x+7,WW-1);
    for(int xx=lo;xx<=hi;xx++){
        float r = g_Ra[bk*NPIX + y*WW + xx];
        float l = g_Lp[b*NPIX + y*WW + xx];
        s0+=r; s1+=r*l; s2+=r*l*l;
    }
    g_t0[bk*NPIX+p]=s0; g_t1[bk*NPIX+p]=s1; g_t2[bk*NPIX+p]=s2;
}

__global__ void kBoxV(){
    int bk = blockIdx.y; int b=bk>>1;
    int p = blockIdx.x*blockDim.x + threadIdx.x;
    if(p >= NPIX) return;
    int y = p / WW, x = p % WW;
    float s0=0.f,s1=0.f,s2=0.f;
    int lo = max(y-7,0), hi = min(y+7,HH-1);
    for(int yy=lo;yy<=hi;yy++){
        s0+=g_t0[bk*NPIX+yy*WW+x]; s1+=g_t1[bk*NPIX+yy*WW+x]; s2+=g_t2[bk*NPIX+yy*WW+x];
    }
    float cy = (float)(min(y+8,HH)-max(y-7,0));
    float cx = (float)(min(x+8,WW)-max(x-7,0));
    float c = cy*cx;
    float a0=s0/c, a1=s1/c, a2=s2/c;
    float den = a0 + 1e-8f;
    float mu = a1/den;
    float vb = fmaxf(a2/den - mu*mu, 1e-8f);
    g_lla[bk*NPIX+p] = fabsf(g_Lp[b*NPIX+p]-mu)/(sqrtf(vb)+1e-8f);
    g_den[bk*NPIX+p] = a0;
}

__global__ void kMinMax(){
    int b = blockIdx.y;
    unsigned mn=0xFFFFFFFFu, mx=0u;
    int per = (NPIX + gridDim.x - 1)/gridDim.x;
    int lo = blockIdx.x*per, hi = min(lo+per, NPIX);
    for(int p=lo+threadIdx.x;p<hi;p+=blockDim.x){
        unsigned k = f2u(g_Lp[b*NPIX+p]);
        mn = min(mn,k); mx = max(mx,k);
    }
    __shared__ unsigned smn[256], smx[256];
    smn[threadIdx.x]=mn; smx[threadIdx.x]=mx;
    __syncthreads();
    for(int o=128;o>0;o>>=1){
        if(threadIdx.x<o){ smn[threadIdx.x]=min(smn[threadIdx.x],smn[threadIdx.x+o]);
                           smx[threadIdx.x]=max(smx[threadIdx.x],smx[threadIdx.x+o]); }
        __syncthreads();
    }
    if(threadIdx.x==0){ atomicMin(&g_mm[b][0],smn[0]); atomicMax(&g_mm[b][1],smx[0]); }
}

__global__ void kBinIdx(){
    int idx = blockIdx.x*blockDim.x + threadIdx.x;
    if(idx >= BN) return;
    int b = idx / NPIX;
    float mn = u2f(g_mm[b][0]), mx = u2f(g_mm[b][1]);
    float ln = (g_Lp[idx]-mn)/(mx-mn+1e-8f);
    ln = fminf(fmaxf(ln,0.f),1.f);
    int c = (int)(ln*32.f);
    g_idxb[idx] = (unsigned char)(c<0?0:(c>31?31:c));
}

__global__ void kGhist(){
    int bk = blockIdx.y; int b=bk>>1;
    __shared__ float sh[32];
    if(threadIdx.x<32) sh[threadIdx.x]=0.f;
    __syncthreads();
    int per = (NPIX + gridDim.x - 1)/gridDim.x;
    int lo = blockIdx.x*per, hi = min(lo+per, NPIX);
    for(int p=lo+threadIdx.x;p<hi;p+=blockDim.x)
        atomicAdd(&sh[g_idxb[b*NPIX+p]], g_Ra[bk*NPIX+p]);
    __syncthreads();
    if(threadIdx.x<32) atomicAdd(&g_ghist[b][bk&1][threadIdx.x],(double)sh[threadIdx.x]);
}

__global__ void kGcdf(){
    int t = threadIdx.x; if(t>=4) return;
    int b=t>>1, k=t&1;
    double tot=0; for(int c=0;c<32;c++) tot += g_ghist[b][k][c];
    double cum=0;
    for(int c=0;c<32;c++){ cum += g_ghist[b][k][c]/(tot+1e-8); g_gcdf[b][k][c]=(float)cum; g_ghist[b][k][c]=0.0; }
    if(k==0){ g_mm[b][0]=0xFFFFFFFFu; g_mm[b][1]=0u; }
}

__global__ void kColHist(){
    int bk = blockIdx.y; int b=bk>>1;
    int warp = threadIdx.x>>5, lane = threadIdx.x&31;
    int x = blockIdx.x*4 + warp;
    if(x >= WW) return;
    const float* rk = g_Ra + bk*NPIX;
    const unsigned char* bi = g_idxb + b*NPIX;
    float hist = 0.f;
    for(int r=0;r<7;r++){
        float v = rk[r*WW+x]; int bn = bi[r*WW+x];
        if(lane==bn) hist += v;
    }
    for(int y=0;y<HH;y++){
        int ra = y+7;
        if(ra<HH){ float v=rk[ra*WW+x]; int bn=bi[ra*WW+x]; if(lane==bn) hist += v; }
        g_colsum[((size_t)(bk*HH+y)*WW + x)*32 + lane] = hist;
        int rr = y-7;
        if(rr>=0){ float v=rk[rr*WW+x]; int bn=bi[rr*WW+x]; if(lane==bn) hist -= v; }
    }
}

__global__ void kGLD(){
    int bk = blockIdx.y; int b=bk>>1, k=bk&1;
    int warp = threadIdx.x>>5, lane = threadIdx.x&31;
    int y = blockIdx.x*4 + warp;
    if(y >= HH) return;
    const float* cs = g_colsum + (size_t)(bk*HH+y)*WW*32;
    float gc = g_gcdf[b][k][lane];
    float S = 0.f;
    for(int xx=0;xx<7;xx++) S += cs[xx*32+lane];
    float cy = (float)(min(y+8,HH)-max(y-7,0));
    for(int x=0;x<WW;x++){
        if(x+7<WW) S += cs[(x+7)*32+lane];
        float c = S;
        for(int o=1;o<32;o<<=1){ float t2=__shfl_up_sync(0xffffffffu,c,o); if(lane>=o) c+=t2; }
        float cx = (float)(min(x+8,WW)-max(x-7,0));
        float den = g_den[bk*NPIX + y*WW+x] + 1e-8f;
        float diff = fabsf(c/(cy*cx)/den - gc);
        for(int o=16;o;o>>=1) diff += __shfl_down_sync(0xffffffffu,diff,o);
        if(lane==0) g_gld[bk*NPIX + y*WW+x] = diff/32.f;
        if(x-7>=0) S -= cs[(x-7)*32+lane];
    }
}

__global__ void kESacc(){
    int b = blockIdx.y;
    float mdE=g_sv[b*3+1], mdS=g_sv[b*3+2];
    float sdE=g_sv[6+b*3+1]*1.4826f+1e-8f, sdS=g_sv[6+b*3+2]*1.4826f+1e-8f;
    double a[5]={0,0,0,0,0};
    int per = (NPIX + gridDim.x - 1)/gridDim.x;
    int lo = blockIdx.x*per, hi = min(lo+per, NPIX);
    for(int p=lo+threadIdx.x;p<hi;p+=blockDim.x){
        float e=(g_E[b*NPIX+p]-mdE)/sdE, s=(g_S[b*NPIX+p]-mdS)/sdS;
        a[0]+=e; a[1]+=s; a[2]+=(double)e*e; a[3]+=(double)e*s; a[4]+=(double)s*s;
    }
    for(int m=0;m<5;m++){ double r=blockReduceD(a[m]); if(threadIdx.x==0) atomicAdd(&g_cacc[b][m],r); }
}

__global__ void kESinv(){
    int b = threadIdx.x; if(b>=BB) return;
    double N=(double)NPIX;
    double mE=g_cacc[b][0]/N, mS=g_cacc[b][1]/N;
    double c00=g_cacc[b][2]/N-mE*mE+1e-6, c01=g_cacc[b][3]/N-mE*mS, c11=g_cacc[b][4]/N-mS*mS+1e-6;
    double det=c00*c11-c01*c01;
    g_esinv[b][0]=c11/det; g_esinv[b][1]=-c01/det; g_esinv[b][2]=c00/det;
    g_esinv[b][3]=mE; g_esinv[b][4]=mS;
    for(int m=0;m<9;m++) g_cacc[b][m]=0.0;
}

__global__ void kGamma(){
    int idx = blockIdx.x*blockDim.x + threadIdx.x;
    if(idx >= BN) return;
    int b = idx / NPIX, p = idx % NPIX;
    float gamma = 1.f;
    for(int k=0;k<2;k++){
        int s = b*2+k;
        float zl = (g_lla[s*NPIX+p]-g_sv[20+s])/(g_sv[24+s]*1.4826f+1e-8f);
        float zg = (g_gld[s*NPIX+p]-g_sv[28+s])/(g_sv[32+s]*1.4826f+1e-8f);
        gamma += g_Ra[s*NPIX+p]*(0.5f*softplusf(zl)+0.5f*softplusf(zg));
    }
    float mdE=g_sv[b*3+1], mdS=g_sv[b*3+2];
    float sdE=g_sv[6+b*3+1]*1.4826f+1e-8f, sdS=g_sv[6+b*3+2]*1.4826f+1e-8f;
    float dE=(g_E[idx]-mdE)/sdE-(float)g_esinv[b][3];
    float dS=(g_S[idx]-mdS)/sdS-(float)g_esinv[b][4];
    float d2 = dE*dE*(float)g_esinv[b][0] + 2.f*dE*dS*(float)g_esinv[b][1] + dS*dS*(float)g_esinv[b][2];
    float Rs = expf(-0.5f*d2);
    g_La[idx] = fmaxf(g_DM[idx]*gamma*(1.f-Rs), 0.f);
}

__global__ void kFinal(float* out){
    int idx = blockIdx.x*blockDim.x + threadIdx.x;
    if(idx >= BN) return;
    int b = idx / NPIX;
    float q1 = g_sv[36+4*b] + 0.55f*(g_sv[37+4*b]-g_sv[36+4*b]);
    float q9 = g_sv[38+4*b] + 0.45f*(g_sv[39+4*b]-g_sv[38+4*b]);
    float v = (g_La[idx]-q1)/(q9-q1+1e-8f);
    out[BN + idx] = fminf(fmaxf(v,0.f),1.f);   // output #2
}

// ======================= host =======================
extern "C" void kernel_launch(void* const* d_in, const int* in_sizes, int n_in,
                              void* d_out, int out_size){
    const float* lab   = (const float*)d_in[0];
    const float* arand = (const float*)d_in[1];
    float* out = (float*)d_out;
    const int EB = (BN+255)/256;      // 1152

    auto selPhase = [&](int start, int cnt){
        for(int p=0;p<4;p++){
            selCount<<<dim3(cnt,16),256>>>(start,p);
            selPick<<<cnt,256>>>(start,p);
        }
    };

    kSobel<<<EB,256>>>(lab);
    kE<<<EB,256>>>();
    kRegAcc<<<dim3(32,BB),256>>>(lab);
    kSolve<<<1,32>>>();
    kLperp<<<EB,256>>>(lab,out);

    selPhase(0,6);       // medians of Lp,E,S
    selPhase(6,6);       // MADs

    kCovAcc<<<dim3(32,BB),256>>>();
    kEigh<<<1,32>>>();
    kCdir<<<1,256>>>(arand);
    kKurtAcc<<<dim3(32,16,BB),256>>>();
    kKurtPick<<<1,32>>>();
    kZb<<<EB,256>>>();

    selPhase(12,8);      // z_best quartile brackets
    kEMinit<<<1,32>>>();
    for(int it=0; it<9; it++){
        kEMacc<<<dim3(32,BB),256>>>();
        kEMupd<<<1,32>>>();
    }
    kRfinal<<<EB,256>>>();
    kRalpha<<<EB,256>>>();

    kClusterAcc<<<dim3(32,4),256>>>();
    kClusterInv<<<1,32>>>();
    kDM<<<EB,256>>>();

    kBoxH<<<dim3((NPIX+255)/256,4),256>>>();
    kBoxV<<<dim3((NPIX+255)/256,4),256>>>();
    selPhase(20,4);      // LLA medians
    selPhase(24,4);      // LLA MADs

    kMinMax<<<dim3(16,BB),256>>>();
    kBinIdx<<<EB,256>>>();
    kGhist<<<dim3(32,4),256>>>();
    kGcdf<<<1,32>>>();
    kColHist<<<dim3(96,4),128>>>();
    kGLD<<<dim3(96,4),128>>>();
    selPhase(28,4);      // GLD medians
    selPhase(32,4);      // GLD MADs

    kESacc<<<dim3(32,BB),256>>>();
    kESinv<<<1,32>>>();
    kGamma<<<EB,256>>>();

    selPhase(36,8);      // L_anom quantile brackets
    kFinal<<<EB,256>>>(out);
}